// round 1
// baseline (speedup 1.0000x reference)
#include <cuda_runtime.h>

#define BB 8
#define NN 20000
#define DD 640
#define RR 2500
#define BINS 10
#define HID 128
#define CONDD 3
#define EPSV 1e-5f

// ---------------- scratch (no allocation allowed) ----------------
__device__ float g_pooled[BB * RR * BINS];   // segment+bin sums
__device__ int   g_counts[RR];
__device__ float g_A[BB * RR * HID];         // pooled part of hidden pre-activation
__device__ float g_C[(size_t)NN * HID];      // conditioner part + b1
__device__ float g_sum[HID];
__device__ float g_sumsq[HID];
__device__ float g_W2p[HID * 3];             // folded layernorm*W2
__device__ float g_b2p[3];

// ---------------- K0: zero scratch accumulators ----------------
__global__ void k_zero() {
    int i = blockIdx.x * blockDim.x + threadIdx.x;
    const int total = BB * RR * BINS;
    for (int j = i; j < total; j += gridDim.x * blockDim.x) g_pooled[j] = 0.0f;
    if (i < RR) g_counts[i] = 0;
    if (i < HID) { g_sum[i] = 0.0f; g_sumsq[i] = 0.0f; }
}

// ---------------- K1: residue counts ----------------
__global__ void k_counts(const int* __restrict__ res_id) {
    int i = blockIdx.x * blockDim.x + threadIdx.x;
    if (i < NN) atomicAdd(&g_counts[res_id[i]], 1);
}

// ---------------- K2: pooling (dominant, reads all of x) ----------------
// One warp per (b, atom) row: 160 float4 = 2560B, fully coalesced.
// Lane l handles float4 items l, l+32, ..., l+128. Item i -> bin i/16, so the
// two 16-lane halves each own 5 fixed bins; shuffle-reduce within 16 lanes,
// then 2 lanes do 5 atomicAdds each (10 atomics/row, spread over 200K addrs).
__global__ void k_pool(const float4* __restrict__ x4, const int* __restrict__ res_id) {
    int w = (blockIdx.x * blockDim.x + threadIdx.x) >> 5;
    int lane = threadIdx.x & 31;
    if (w >= BB * NN) return;
    int b = w / NN;
    int n = w - b * NN;
    int rid = res_id[n];
    const float4* row = x4 + (size_t)w * (DD / 4);

    float s[5];
#pragma unroll
    for (int k = 0; k < 5; k++) {
        float4 v = row[lane + 32 * k];
        s[k] = (v.x + v.y) + (v.z + v.w);
    }
#pragma unroll
    for (int k = 0; k < 5; k++) {
#pragma unroll
        for (int off = 8; off >= 1; off >>= 1)
            s[k] += __shfl_down_sync(0xffffffffu, s[k], off, 16);
    }
    if ((lane & 15) == 0) {
        int half = lane >> 4;                 // 0 -> even bins, 1 -> odd bins
        float* dst = &g_pooled[((size_t)b * RR + rid) * BINS];
#pragma unroll
        for (int k = 0; k < 5; k++)
            atomicAdd(&dst[2 * k + half], s[k]);
    }
}

// ---------------- K3: A = pooled_mean @ W1[:10] ----------------
__global__ void k_A(const float* __restrict__ W1) {
    int row = blockIdx.x;            // b*RR + r
    int r = row % RR;
    int h = threadIdx.x;             // 128
    __shared__ float p[BINS];
    if (h < BINS) p[h] = g_pooled[(size_t)row * BINS + h] / ((float)g_counts[r] * 64.0f);
    __syncthreads();
    float acc = 0.0f;
#pragma unroll
    for (int j = 0; j < BINS; j++) acc = fmaf(p[j], W1[j * HID + h], acc);
    g_A[(size_t)row * HID + h] = acc;
}

// ---------------- K4: C = cond @ W1[10:13] + b1 ----------------
__global__ void k_C(const float* __restrict__ cond, const float* __restrict__ W1,
                    const float* __restrict__ b1) {
    int n = blockIdx.x;
    int h = threadIdx.x;
    float c0 = cond[n * 3 + 0], c1 = cond[n * 3 + 1], c2 = cond[n * 3 + 2];
    float v = b1[h];
    v = fmaf(c0, W1[10 * HID + h], v);
    v = fmaf(c1, W1[11 * HID + h], v);
    v = fmaf(c2, W1[12 * HID + h], v);
    g_C[(size_t)n * HID + h] = v;
}

// ---------------- K5: global per-feature sum / sumsq of relu(A+C) ----------------
__global__ void k_stats(const int* __restrict__ res_id) {
    __shared__ float ssum[HID];
    __shared__ float ssq[HID];
    int t = threadIdx.x;
    if (t < HID) { ssum[t] = 0.0f; ssq[t] = 0.0f; }
    __syncthreads();

    int lane = t & 31;
    int wid_g = (blockIdx.x * blockDim.x + t) >> 5;
    int nwarps = (gridDim.x * blockDim.x) >> 5;

    float ls[4] = {0, 0, 0, 0}, lq[4] = {0, 0, 0, 0};
    for (int row = wid_g; row < BB * NN; row += nwarps) {
        int b = row / NN;
        int n = row - b * NN;
        int rid = res_id[n];
        const float* Ar = &g_A[((size_t)b * RR + rid) * HID];
        const float* Cr = &g_C[(size_t)n * HID];
#pragma unroll
        for (int k = 0; k < 4; k++) {
            int f = lane + 32 * k;
            float v = fmaxf(Ar[f] + Cr[f], 0.0f);
            ls[k] += v;
            lq[k] = fmaf(v, v, lq[k]);
        }
    }
#pragma unroll
    for (int k = 0; k < 4; k++) {
        atomicAdd(&ssum[lane + 32 * k], ls[k]);
        atomicAdd(&ssq[lane + 32 * k], lq[k]);
    }
    __syncthreads();
    if (t < HID) {
        atomicAdd(&g_sum[t], ssum[t]);
        atomicAdd(&g_sumsq[t], ssq[t]);
    }
}

// ---------------- K6: fold layernorm into W2/b2 ----------------
__global__ void k_final(const float* __restrict__ gamma, const float* __restrict__ beta,
                        const float* __restrict__ W2, const float* __restrict__ b2) {
    int f = threadIdx.x;  // 128
    const float inv = 1.0f / (float)(BB * NN);
    float mu = g_sum[f] * inv;
    float var = g_sumsq[f] * inv - mu * mu;
    float s = rsqrtf(var + EPSV) * gamma[f];
    float off = beta[f] - mu * s;
    float w0 = W2[f * 3 + 0], w1 = W2[f * 3 + 1], w2 = W2[f * 3 + 2];
    g_W2p[f * 3 + 0] = w0 * s;
    g_W2p[f * 3 + 1] = w1 * s;
    g_W2p[f * 3 + 2] = w2 * s;

    __shared__ float red[3][HID];
    red[0][f] = off * w0;
    red[1][f] = off * w1;
    red[2][f] = off * w2;
    __syncthreads();
    for (int st = 64; st >= 1; st >>= 1) {
        if (f < st) {
            red[0][f] += red[0][f + st];
            red[1][f] += red[1][f + st];
            red[2][f] += red[2][f + st];
        }
        __syncthreads();
    }
    if (f < 3) g_b2p[f] = b2[f] + red[f][0];
}

// ---------------- K7: output = relu(A+C) @ W2p + b2p ----------------
__global__ void k_out(const int* __restrict__ res_id, float* __restrict__ out) {
    int t = threadIdx.x;
    int lane = t & 31;
    int wid_g = (blockIdx.x * blockDim.x + t) >> 5;
    int nwarps = (gridDim.x * blockDim.x) >> 5;

    float w[4][3];
#pragma unroll
    for (int k = 0; k < 4; k++) {
        int f = lane + 32 * k;
        w[k][0] = g_W2p[f * 3 + 0];
        w[k][1] = g_W2p[f * 3 + 1];
        w[k][2] = g_W2p[f * 3 + 2];
    }
    float bb0 = g_b2p[0], bb1 = g_b2p[1], bb2 = g_b2p[2];

    for (int row = wid_g; row < BB * NN; row += nwarps) {
        int b = row / NN;
        int n = row - b * NN;
        int rid = res_id[n];
        const float* Ar = &g_A[((size_t)b * RR + rid) * HID];
        const float* Cr = &g_C[(size_t)n * HID];
        float o0 = 0, o1 = 0, o2 = 0;
#pragma unroll
        for (int k = 0; k < 4; k++) {
            int f = lane + 32 * k;
            float v = fmaxf(Ar[f] + Cr[f], 0.0f);
            o0 = fmaf(v, w[k][0], o0);
            o1 = fmaf(v, w[k][1], o1);
            o2 = fmaf(v, w[k][2], o2);
        }
#pragma unroll
        for (int off = 16; off >= 1; off >>= 1) {
            o0 += __shfl_down_sync(0xffffffffu, o0, off);
            o1 += __shfl_down_sync(0xffffffffu, o1, off);
            o2 += __shfl_down_sync(0xffffffffu, o2, off);
        }
        if (lane == 0) {
            float* p = out + (size_t)row * 3;
            p[0] = o0 + bb0;
            p[1] = o1 + bb1;
            p[2] = o2 + bb2;
        }
    }
}

// ---------------- launcher ----------------
extern "C" void kernel_launch(void* const* d_in, const int* in_sizes, int n_in,
                              void* d_out, int out_size) {
    const float* x     = (const float*)d_in[0];
    const float* cond  = (const float*)d_in[1];
    const int*   resid = (const int*)d_in[2];
    const float* W1    = (const float*)d_in[3];
    const float* b1    = (const float*)d_in[4];
    const float* gamma = (const float*)d_in[5];
    const float* beta  = (const float*)d_in[6];
    const float* W2    = (const float*)d_in[7];
    const float* b2    = (const float*)d_in[8];
    float* out = (float*)d_out;

    (void)in_sizes; (void)n_in; (void)out_size;

    k_zero<<<(BB * RR * BINS + 255) / 256, 256>>>();
    k_counts<<<(NN + 255) / 256, 256>>>(resid);
    // one warp per (b, atom) row: BB*NN warps, 8 warps/block
    k_pool<<<(BB * NN + 7) / 8, 256>>>((const float4*)x, resid);
    k_A<<<BB * RR, HID>>>(W1);
    k_C<<<NN, HID>>>(cond, W1, b1);
    k_stats<<<592, 256>>>(resid);
    k_final<<<1, HID>>>(gamma, beta, W2, b2);
    k_out<<<1184, 256>>>(resid, out);
}

// round 2
// speedup vs baseline: 1.2674x; 1.2674x over previous
#include <cuda_runtime.h>

#define BB 8
#define NN 20000
#define DD 640
#define RR 2500
#define BINS 10
#define HID 128
#define EPSV 1e-5f

// ---------------- scratch (no allocation allowed) ----------------
__device__ float g_pooled[BB * RR * BINS];   // segment+bin sums
__device__ int   g_off[RR + 1];              // segment start offsets (res_id sorted)
__device__ float g_sum[HID];
__device__ float g_sumsq[HID];
__device__ float g_W2p[HID * 3];             // folded layernorm*W2
__device__ float g_b2p[3];

// ---------------- K0: zero scratch accumulators ----------------
__global__ void k_zero() {
    int i = blockIdx.x * blockDim.x + threadIdx.x;
    const int total = BB * RR * BINS;
    if (i < total) g_pooled[i] = 0.0f;
    if (i < HID) { g_sum[i] = 0.0f; g_sumsq[i] = 0.0f; }
}

// ---------------- K1: segment offsets from sorted res_id ----------------
__global__ void k_offsets(const int* __restrict__ res_id) {
    int i = blockIdx.x * blockDim.x + threadIdx.x;
    if (i < NN) {
        int r = res_id[i];
        if (i == 0 || res_id[i - 1] != r) g_off[r] = i;
    }
    if (i == 0) g_off[RR] = NN;
}

// ---------------- K2: pooling (dominant, reads all of x) ----------------
// One warp per (b, atom) row: 160 float4 = 2560B, fully coalesced.
// Lane l handles float4 items l, l+32, ..., l+128. Item i -> bin i/16; the
// two 16-lane halves each own 5 fixed bins; shuffle-reduce within 16 lanes,
// then 2 lanes do 5 atomicAdds each (10 atomics/row, spread over 200K addrs).
__global__ void k_pool(const float4* __restrict__ x4, const int* __restrict__ res_id) {
    int w = (blockIdx.x * blockDim.x + threadIdx.x) >> 5;
    int lane = threadIdx.x & 31;
    if (w >= BB * NN) return;
    int b = w / NN;
    int n = w - b * NN;
    int rid = res_id[n];
    const float4* row = x4 + (size_t)w * (DD / 4);

    float s[5];
#pragma unroll
    for (int k = 0; k < 5; k++) {
        float4 v = __ldg(&row[lane + 32 * k]);
        s[k] = (v.x + v.y) + (v.z + v.w);
    }
#pragma unroll
    for (int k = 0; k < 5; k++) {
#pragma unroll
        for (int off = 8; off >= 1; off >>= 1)
            s[k] += __shfl_down_sync(0xffffffffu, s[k], off, 16);
    }
    if ((lane & 15) == 0) {
        int half = lane >> 4;                 // 0 -> even bins, 1 -> odd bins
        float* dst = &g_pooled[((size_t)b * RR + rid) * BINS];
#pragma unroll
        for (int k = 0; k < 5; k++)
            atomicAdd(&dst[2 * k + half], s[k]);
    }
}

// ---------------- K3: per-feature sum / sumsq of relu(h) ----------------
// One warp per (b, residue) segment, grid-stride. Hidden pre-activation
// computed entirely in registers from pooled (10 vals) + cond (3 vals/atom).
__global__ void __launch_bounds__(256) k_stats(const float* __restrict__ cond,
                                               const float* __restrict__ W1,
                                               const float* __restrict__ b1) {
    __shared__ float ssum[HID];
    __shared__ float ssq[HID];
    int t = threadIdx.x;
    if (t < HID) { ssum[t] = 0.0f; ssq[t] = 0.0f; }
    __syncthreads();
    int lane = t & 31;

    float w1p[BINS][4], w1c[3][4], bb[4];
#pragma unroll
    for (int j = 0; j < BINS; j++)
#pragma unroll
        for (int k = 0; k < 4; k++) w1p[j][k] = __ldg(&W1[j * HID + lane + 32 * k]);
#pragma unroll
    for (int j = 0; j < 3; j++)
#pragma unroll
        for (int k = 0; k < 4; k++) w1c[j][k] = __ldg(&W1[(BINS + j) * HID + lane + 32 * k]);
#pragma unroll
    for (int k = 0; k < 4; k++) bb[k] = __ldg(&b1[lane + 32 * k]);

    float ls[4] = {0, 0, 0, 0}, lq[4] = {0, 0, 0, 0};
    int warp = (blockIdx.x * blockDim.x + t) >> 5;
    int nw = (gridDim.x * blockDim.x) >> 5;

    for (int s = warp; s < BB * RR; s += nw) {
        int r = s % RR;
        int o0 = g_off[r], o1 = g_off[r + 1];
        float inv = 1.0f / ((float)(o1 - o0) * 64.0f);
        float a[4];
#pragma unroll
        for (int k = 0; k < 4; k++) a[k] = bb[k];
#pragma unroll
        for (int j = 0; j < BINS; j++) {
            float p = g_pooled[(size_t)s * BINS + j] * inv;
#pragma unroll
            for (int k = 0; k < 4; k++) a[k] = fmaf(p, w1p[j][k], a[k]);
        }
        for (int n = o0; n < o1; n++) {
            float c0 = __ldg(&cond[n * 3 + 0]);
            float c1 = __ldg(&cond[n * 3 + 1]);
            float c2 = __ldg(&cond[n * 3 + 2]);
#pragma unroll
            for (int k = 0; k < 4; k++) {
                float v = fmaf(c0, w1c[0][k], fmaf(c1, w1c[1][k], fmaf(c2, w1c[2][k], a[k])));
                v = fmaxf(v, 0.0f);
                ls[k] += v;
                lq[k] = fmaf(v, v, lq[k]);
            }
        }
    }
#pragma unroll
    for (int k = 0; k < 4; k++) {
        atomicAdd(&ssum[lane + 32 * k], ls[k]);
        atomicAdd(&ssq[lane + 32 * k], lq[k]);
    }
    __syncthreads();
    if (t < HID) {
        atomicAdd(&g_sum[t], ssum[t]);
        atomicAdd(&g_sumsq[t], ssq[t]);
    }
}

// ---------------- K4: fold layernorm into W2/b2 ----------------
__global__ void k_final(const float* __restrict__ gamma, const float* __restrict__ beta,
                        const float* __restrict__ W2, const float* __restrict__ b2) {
    int f = threadIdx.x;  // 128
    const float inv = 1.0f / (float)(BB * NN);
    float mu = g_sum[f] * inv;
    float var = g_sumsq[f] * inv - mu * mu;
    float s = rsqrtf(var + EPSV) * gamma[f];
    float off = beta[f] - mu * s;
    float w0 = W2[f * 3 + 0], w1 = W2[f * 3 + 1], w2 = W2[f * 3 + 2];
    g_W2p[f * 3 + 0] = w0 * s;
    g_W2p[f * 3 + 1] = w1 * s;
    g_W2p[f * 3 + 2] = w2 * s;

    __shared__ float red[3][HID];
    red[0][f] = off * w0;
    red[1][f] = off * w1;
    red[2][f] = off * w2;
    __syncthreads();
    for (int st = 64; st >= 1; st >>= 1) {
        if (f < st) {
            red[0][f] += red[0][f + st];
            red[1][f] += red[1][f + st];
            red[2][f] += red[2][f + st];
        }
        __syncthreads();
    }
    if (f < 3) g_b2p[f] = b2[f] + red[f][0];
}

// ---------------- K5: output = relu(h) @ W2p + b2p ----------------
__global__ void __launch_bounds__(256) k_out(const float* __restrict__ cond,
                                             const float* __restrict__ W1,
                                             const float* __restrict__ b1,
                                             float* __restrict__ out) {
    int t = threadIdx.x;
    int lane = t & 31;

    float w1p[BINS][4], w1c[3][4], bb[4], w2[4][3];
#pragma unroll
    for (int j = 0; j < BINS; j++)
#pragma unroll
        for (int k = 0; k < 4; k++) w1p[j][k] = __ldg(&W1[j * HID + lane + 32 * k]);
#pragma unroll
    for (int j = 0; j < 3; j++)
#pragma unroll
        for (int k = 0; k < 4; k++) w1c[j][k] = __ldg(&W1[(BINS + j) * HID + lane + 32 * k]);
#pragma unroll
    for (int k = 0; k < 4; k++) {
        int f = lane + 32 * k;
        bb[k] = __ldg(&b1[f]);
        w2[k][0] = g_W2p[f * 3 + 0];
        w2[k][1] = g_W2p[f * 3 + 1];
        w2[k][2] = g_W2p[f * 3 + 2];
    }
    float bo0 = g_b2p[0], bo1 = g_b2p[1], bo2 = g_b2p[2];

    int warp = (blockIdx.x * blockDim.x + t) >> 5;
    int nw = (gridDim.x * blockDim.x) >> 5;

    for (int s = warp; s < BB * RR; s += nw) {
        int b = s / RR;
        int r = s - b * RR;
        int o0 = g_off[r], o1 = g_off[r + 1];
        float inv = 1.0f / ((float)(o1 - o0) * 64.0f);
        float a[4];
#pragma unroll
        for (int k = 0; k < 4; k++) a[k] = bb[k];
#pragma unroll
        for (int j = 0; j < BINS; j++) {
            float p = g_pooled[(size_t)s * BINS + j] * inv;
#pragma unroll
            for (int k = 0; k < 4; k++) a[k] = fmaf(p, w1p[j][k], a[k]);
        }
        for (int n = o0; n < o1; n++) {
            float c0 = __ldg(&cond[n * 3 + 0]);
            float c1 = __ldg(&cond[n * 3 + 1]);
            float c2 = __ldg(&cond[n * 3 + 2]);
            float y0 = 0.0f, y1 = 0.0f, y2 = 0.0f;
#pragma unroll
            for (int k = 0; k < 4; k++) {
                float v = fmaf(c0, w1c[0][k], fmaf(c1, w1c[1][k], fmaf(c2, w1c[2][k], a[k])));
                v = fmaxf(v, 0.0f);
                y0 = fmaf(v, w2[k][0], y0);
                y1 = fmaf(v, w2[k][1], y1);
                y2 = fmaf(v, w2[k][2], y2);
            }
#pragma unroll
            for (int off = 16; off >= 1; off >>= 1) {
                y0 += __shfl_down_sync(0xffffffffu, y0, off);
                y1 += __shfl_down_sync(0xffffffffu, y1, off);
                y2 += __shfl_down_sync(0xffffffffu, y2, off);
            }
            if (lane == 0) {
                float* p = out + ((size_t)b * NN + n) * 3;
                p[0] = y0 + bo0;
                p[1] = y1 + bo1;
                p[2] = y2 + bo2;
            }
        }
    }
}

// ---------------- launcher ----------------
extern "C" void kernel_launch(void* const* d_in, const int* in_sizes, int n_in,
                              void* d_out, int out_size) {
    const float* x     = (const float*)d_in[0];
    const float* cond  = (const float*)d_in[1];
    const int*   resid = (const int*)d_in[2];
    const float* W1    = (const float*)d_in[3];
    const float* b1    = (const float*)d_in[4];
    const float* gamma = (const float*)d_in[5];
    const float* beta  = (const float*)d_in[6];
    const float* W2    = (const float*)d_in[7];
    const float* b2    = (const float*)d_in[8];
    float* out = (float*)d_out;

    (void)in_sizes; (void)n_in; (void)out_size;

    k_zero<<<(BB * RR * BINS + 255) / 256, 256>>>();
    k_offsets<<<(NN + 255) / 256, 256>>>(resid);
    k_pool<<<(BB * NN + 7) / 8, 256>>>((const float4*)x, resid);
    k_stats<<<296, 256>>>(cond, W1, b1);
    k_final<<<1, HID>>>(gamma, beta, W2, b2);
    k_out<<<296, 256>>>(cond, W1, b1, out);
}

// round 4
// speedup vs baseline: 1.5103x; 1.1917x over previous
#include <cuda_runtime.h>

#define BB 8
#define NN 20000
#define DD 640
#define RR 2500
#define BINS 10
#define HID 128
#define EPSV 1e-5f

typedef unsigned long long ull;

// ---------------- scratch (no allocation allowed) ----------------
__device__ float g_pooled[RR * BB * BINS];   // [r][b][bin] segment sums
__device__ int   g_off[RR + 1];              // segment offsets (res_id sorted)
__device__ float g_sum[HID];
__device__ float g_sumsq[HID];

// ---------------- packed f32x2 helpers (sm_100+) ----------------
__device__ __forceinline__ ull pk2(float lo, float hi) {
    ull r; asm("mov.b64 %0,{%1,%2};" : "=l"(r) : "f"(lo), "f"(hi)); return r;
}
__device__ __forceinline__ void upk2(ull v, float& lo, float& hi) {
    asm("mov.b64 {%0,%1},%2;" : "=f"(lo), "=f"(hi) : "l"(v));
}
__device__ __forceinline__ ull add2(ull a, ull b) {
    ull d; asm("add.rn.f32x2 %0,%1,%2;" : "=l"(d) : "l"(a), "l"(b)); return d;
}
__device__ __forceinline__ ull mul2(ull a, ull b) {
    ull d; asm("mul.rn.f32x2 %0,%1,%2;" : "=l"(d) : "l"(a), "l"(b)); return d;
}
__device__ __forceinline__ ull fma2(ull a, ull b, ull c) {
    ull d; asm("fma.rn.f32x2 %0,%1,%2,%3;" : "=l"(d) : "l"(a), "l"(b), "l"(c)); return d;
}
// relu on a packed pair: unpack (reg-rename, free), 2x FMNMX, repack (free)
__device__ __forceinline__ ull relu2(ull a) {
    float lo, hi; upk2(a, lo, hi);
    return pk2(fmaxf(lo, 0.0f), fmaxf(hi, 0.0f));
}

// ---------------- K0: zero accumulators + segment offsets ----------------
__global__ void k_init(const int* __restrict__ res_id) {
    int i = blockIdx.x * blockDim.x + threadIdx.x;
    if (i < RR * BB * BINS) g_pooled[i] = 0.0f;
    if (i < NN) {
        int r = res_id[i];
        if (i == 0 || res_id[i - 1] != r) g_off[r] = i;
    }
    if (i == 0) g_off[RR] = NN;
    if (i < HID) { g_sum[i] = 0.0f; g_sumsq[i] = 0.0f; }
}

// ---------------- K1: pooling (dominant, reads all 410MB of x) ----------------
// One warp per (b, atom) row: 160 float4, fully coalesced. Lane l handles
// float4 items l, l+32k; item i -> bin i/16, the two 16-lane halves each own
// 5 fixed bins; 16-lane shuffle reduce, then 10 atomics/row over 200K addrs.
__global__ void k_pool(const float4* __restrict__ x4, const int* __restrict__ res_id) {
    int w = (blockIdx.x * blockDim.x + threadIdx.x) >> 5;
    int lane = threadIdx.x & 31;
    if (w >= BB * NN) return;
    int b = w / NN;
    int n = w - b * NN;
    int rid = res_id[n];
    const float4* row = x4 + (size_t)w * (DD / 4);

    float s[5];
#pragma unroll
    for (int k = 0; k < 5; k++) {
        float4 v = __ldg(&row[lane + 32 * k]);
        s[k] = (v.x + v.y) + (v.z + v.w);
    }
#pragma unroll
    for (int k = 0; k < 5; k++) {
#pragma unroll
        for (int off = 8; off >= 1; off >>= 1)
            s[k] += __shfl_down_sync(0xffffffffu, s[k], off, 16);
    }
    if ((lane & 15) == 0) {
        int half = lane >> 4;
        float* dst = &g_pooled[((size_t)rid * BB + b) * BINS];
#pragma unroll
        for (int k = 0; k < 5; k++)
            atomicAdd(&dst[2 * k + half], s[k]);
    }
}

// Shared prologue: load packed W1 (pairing features (lane,lane+32) k2=0,
// (lane+64,lane+96) k2=1), then per-residue compute a2[b][k2] from pooled.
#define LOAD_W1_PACKED()                                                        \
    ull w1p2[BINS][2], w1c2[3][2], bb2[2];                                      \
    _Pragma("unroll")                                                           \
    for (int j = 0; j < BINS; j++) {                                            \
        w1p2[j][0] = pk2(__ldg(&W1[j * HID + lane]), __ldg(&W1[j * HID + lane + 32]));       \
        w1p2[j][1] = pk2(__ldg(&W1[j * HID + lane + 64]), __ldg(&W1[j * HID + lane + 96]));  \
    }                                                                           \
    _Pragma("unroll")                                                           \
    for (int j = 0; j < 3; j++) {                                               \
        w1c2[j][0] = pk2(__ldg(&W1[(BINS + j) * HID + lane]), __ldg(&W1[(BINS + j) * HID + lane + 32]));      \
        w1c2[j][1] = pk2(__ldg(&W1[(BINS + j) * HID + lane + 64]), __ldg(&W1[(BINS + j) * HID + lane + 96])); \
    }                                                                           \
    bb2[0] = pk2(__ldg(&b1[lane]), __ldg(&b1[lane + 32]));                      \
    bb2[1] = pk2(__ldg(&b1[lane + 64]), __ldg(&b1[lane + 96]));

#define COMPUTE_A2()                                                            \
    int o0 = g_off[r], o1 = g_off[r + 1], cnt = o1 - o0;                        \
    float inv = 1.0f / ((float)cnt * 64.0f);                                    \
    const float* pp = &g_pooled[(size_t)r * BB * BINS];                         \
    float p0 = pp[lane], p1 = pp[lane + 32], p2 = (lane < 16) ? pp[lane + 64] : 0.0f; \
    ull a2[BB][2];                                                              \
    _Pragma("unroll")                                                           \
    for (int b = 0; b < BB; b++) {                                              \
        a2[b][0] = bb2[0]; a2[b][1] = bb2[1];                                   \
        _Pragma("unroll")                                                       \
        for (int j = 0; j < BINS; j++) {                                        \
            int idx = b * BINS + j;                                             \
            float v = __shfl_sync(0xffffffffu, idx < 32 ? p0 : (idx < 64 ? p1 : p2), idx & 31); \
            float pm = v * inv;                                                 \
            ull pm2 = pk2(pm, pm);                                              \
            a2[b][0] = fma2(pm2, w1p2[j][0], a2[b][0]);                         \
            a2[b][1] = fma2(pm2, w1p2[j][1], a2[b][1]);                         \
        }                                                                       \
    }

// ---------------- K2: per-feature sum / sumsq of relu(h) ----------------
// One warp per residue; all 8 batches handled together (cond shared).
__global__ void __launch_bounds__(256) k_stats(const float* __restrict__ cond,
                                               const float* __restrict__ W1,
                                               const float* __restrict__ b1) {
    __shared__ float ssum[HID];
    __shared__ float ssq[HID];
    int t = threadIdx.x;
    if (t < HID) { ssum[t] = 0.0f; ssq[t] = 0.0f; }
    __syncthreads();
    int lane = t & 31;

    LOAD_W1_PACKED();

    ull ls2[2] = {0, 0}, lq2[2] = {0, 0};
    int r = (blockIdx.x * blockDim.x + t) >> 5;
    if (r < RR) {
        COMPUTE_A2();
        float cseg = (lane < 3 * cnt) ? __ldg(&cond[o0 * 3 + lane]) : 0.0f;
        for (int i = 0; i < cnt; i++) {
            float c0 = __shfl_sync(0xffffffffu, cseg, 3 * i);
            float c1 = __shfl_sync(0xffffffffu, cseg, 3 * i + 1);
            float c2 = __shfl_sync(0xffffffffu, cseg, 3 * i + 2);
            ull c02 = pk2(c0, c0), c12 = pk2(c1, c1), c22 = pk2(c2, c2);
#pragma unroll
            for (int k2 = 0; k2 < 2; k2++) {
                ull cc = fma2(c02, w1c2[0][k2], fma2(c12, w1c2[1][k2], mul2(c22, w1c2[2][k2])));
#pragma unroll
                for (int b = 0; b < BB; b++) {
                    ull v = relu2(add2(a2[b][k2], cc));
                    ls2[k2] = add2(ls2[k2], v);
                    lq2[k2] = fma2(v, v, lq2[k2]);
                }
            }
        }
    }
    float x0, x1;
    upk2(ls2[0], x0, x1); atomicAdd(&ssum[lane], x0); atomicAdd(&ssum[lane + 32], x1);
    upk2(ls2[1], x0, x1); atomicAdd(&ssum[lane + 64], x0); atomicAdd(&ssum[lane + 96], x1);
    upk2(lq2[0], x0, x1); atomicAdd(&ssq[lane], x0);  atomicAdd(&ssq[lane + 32], x1);
    upk2(lq2[1], x0, x1); atomicAdd(&ssq[lane + 64], x0); atomicAdd(&ssq[lane + 96], x1);
    __syncthreads();
    if (t < HID) {
        atomicAdd(&g_sum[t], ssum[t]);
        atomicAdd(&g_sumsq[t], ssq[t]);
    }
}

// ---------------- K3: output (layernorm fold recomputed per-warp) ----------------
__global__ void __launch_bounds__(256) k_out(const float* __restrict__ cond,
                                             const float* __restrict__ W1,
                                             const float* __restrict__ b1,
                                             const float* __restrict__ gamma,
                                             const float* __restrict__ beta,
                                             const float* __restrict__ W2,
                                             const float* __restrict__ b2,
                                             float* __restrict__ out) {
    int t = threadIdx.x, lane = t & 31;

    // Fold layernorm into per-feature W2 scale + output bias (redundant per warp).
    float w2s[4][3];
    float offc[3] = {0, 0, 0};
    const float invn = 1.0f / (float)(BB * NN);
#pragma unroll
    for (int k = 0; k < 4; k++) {
        int f = lane + 32 * k;
        float mu = g_sum[f] * invn;
        float var = g_sumsq[f] * invn - mu * mu;
        float s = rsqrtf(var + EPSV) * __ldg(&gamma[f]);
        float off = __ldg(&beta[f]) - mu * s;
#pragma unroll
        for (int j = 0; j < 3; j++) {
            float w = __ldg(&W2[f * 3 + j]);
            w2s[k][j] = w * s;
            offc[j] += off * w;
        }
    }
#pragma unroll
    for (int o = 16; o >= 1; o >>= 1) {
        offc[0] += __shfl_xor_sync(0xffffffffu, offc[0], o);
        offc[1] += __shfl_xor_sync(0xffffffffu, offc[1], o);
        offc[2] += __shfl_xor_sync(0xffffffffu, offc[2], o);
    }
    float bo0 = offc[0] + __ldg(&b2[0]);
    float bo1 = offc[1] + __ldg(&b2[1]);
    float bo2 = offc[2] + __ldg(&b2[2]);

    ull w22[2][3];
#pragma unroll
    for (int j = 0; j < 3; j++) {
        w22[0][j] = pk2(w2s[0][j], w2s[1][j]);
        w22[1][j] = pk2(w2s[2][j], w2s[3][j]);
    }

    LOAD_W1_PACKED();

    int r = (blockIdx.x * blockDim.x + t) >> 5;
    if (r >= RR) return;
    COMPUTE_A2();
    float cseg = (lane < 3 * cnt) ? __ldg(&cond[o0 * 3 + lane]) : 0.0f;

    for (int i = 0; i < cnt; i++) {
        float c0 = __shfl_sync(0xffffffffu, cseg, 3 * i);
        float c1 = __shfl_sync(0xffffffffu, cseg, 3 * i + 1);
        float c2 = __shfl_sync(0xffffffffu, cseg, 3 * i + 2);
        ull c02 = pk2(c0, c0), c12 = pk2(c1, c1), c22 = pk2(c2, c2);
        ull cc[2];
#pragma unroll
        for (int k2 = 0; k2 < 2; k2++)
            cc[k2] = fma2(c02, w1c2[0][k2], fma2(c12, w1c2[1][k2], mul2(c22, w1c2[2][k2])));
#pragma unroll
        for (int b = 0; b < BB; b++) {
            ull y0 = 0, y1 = 0, y2v = 0;
#pragma unroll
            for (int k2 = 0; k2 < 2; k2++) {
                ull v = relu2(add2(a2[b][k2], cc[k2]));
                y0 = fma2(v, w22[k2][0], y0);
                y1 = fma2(v, w22[k2][1], y1);
                y2v = fma2(v, w22[k2][2], y2v);
            }
            float u0, u1;
            upk2(y0, u0, u1);  float r0 = u0 + u1;
            upk2(y1, u0, u1);  float r1 = u0 + u1;
            upk2(y2v, u0, u1); float r2 = u0 + u1;
#pragma unroll
            for (int o = 16; o >= 1; o >>= 1) {
                r0 += __shfl_down_sync(0xffffffffu, r0, o);
                r1 += __shfl_down_sync(0xffffffffu, r1, o);
                r2 += __shfl_down_sync(0xffffffffu, r2, o);
            }
            if (lane == 0) {
                float* p = out + ((size_t)b * NN + (o0 + i)) * 3;
                p[0] = r0 + bo0;
                p[1] = r1 + bo1;
                p[2] = r2 + bo2;
            }
        }
    }
}

// ---------------- launcher ----------------
extern "C" void kernel_launch(void* const* d_in, const int* in_sizes, int n_in,
                              void* d_out, int out_size) {
    const float* x     = (const float*)d_in[0];
    const float* cond  = (const float*)d_in[1];
    const int*   resid = (const int*)d_in[2];
    const float* W1    = (const float*)d_in[3];
    const float* b1    = (const float*)d_in[4];
    const float* gamma = (const float*)d_in[5];
    const float* beta  = (const float*)d_in[6];
    const float* W2    = (const float*)d_in[7];
    const float* b2    = (const float*)d_in[8];
    float* out = (float*)d_out;

    (void)in_sizes; (void)n_in; (void)out_size;

    k_init<<<(RR * BB * BINS + 255) / 256, 256>>>(resid);
    k_pool<<<(BB * NN + 7) / 8, 256>>>((const float4*)x, resid);
    k_stats<<<(RR * 32 + 255) / 256, 256>>>(cond, W1, b1);
    k_out<<<(RR * 32 + 255) / 256, 256>>>(cond, W1, b1, gamma, beta, W2, b2, out);
}